// round 3
// baseline (speedup 1.0000x reference)
#include <cuda_runtime.h>
#include <cuda_fp16.h>
#include <math.h>

#define NT 2000
#define NPT 255
#define NC 16
#define NM 32
#define NG 16

#define BETA_SLOTS 96                         // ping-pong: 64 + 32
#define BETA_HALFS (BETA_SLOTS*256)           // [slot][g][c], half
#define B_HALFS    (NM*NG*NC)                 // [m][g][c], half
#define DYN_BYTES  (BETA_HALFS*2 + B_HALFS*2 + NM*NG*8)  // 49152+16384+4096 = 69632

__device__ float  g_smA[NC*NC*NG];            // softmaxed A, [p][c][g]
__device__ float  g_smBt[NM*NG*NC];           // softmaxed B, transposed [m][g][c]
__device__ float  g_smPi[NC*NG];              // softmaxed Pi, [c][g]
__device__ float2 g_nu[NM*NG];                // leaf {1/nu, log nu} per (m,g)

// ---------------------------------------------------------------------------
// packed f32x2 helpers (FFMA2/FADD2/FMUL2 only reachable via PTX)
// ---------------------------------------------------------------------------
__device__ __forceinline__ unsigned long long pack2(float lo, float hi) {
    unsigned long long r;
    asm("mov.b64 %0, {%1, %2};" : "=l"(r) : "f"(lo), "f"(hi));
    return r;
}
__device__ __forceinline__ void ffma2(unsigned long long& d,
                                      unsigned long long a, unsigned long long b) {
    asm("fma.rn.f32x2 %0, %1, %2, %0;" : "+l"(d) : "l"(a), "l"(b));
}
__device__ __forceinline__ void mul2(unsigned long long& d, unsigned long long a) {
    asm("mul.rn.f32x2 %0, %0, %1;" : "+l"(d) : "l"(a));
}
__device__ __forceinline__ float unpack_sum(unsigned long long v) {
    float lo, hi;
    asm("mov.b64 {%0, %1}, %2;" : "=f"(lo), "=f"(hi) : "l"(v));
    return lo + hi;
}

// ---------------------------------------------------------------------------
// Prologue: softmaxes + transposed B + leaf-nu table. 1 block, 256 threads.
// ---------------------------------------------------------------------------
__global__ void htmm_softmax_kernel(const float* __restrict__ A,
                                    const float* __restrict__ B,
                                    const float* __restrict__ Pi) {
    int tid = threadIdx.x;
    int c = tid >> 4;
    int g = tid & 15;
    {   // A: softmax over p for each (c,g)
        float mx = -1e30f;
        #pragma unroll
        for (int p = 0; p < NC; p++) mx = fmaxf(mx, A[p*NC*NG + c*NG + g]);
        float e[NC]; float s = 0.f;
        #pragma unroll
        for (int p = 0; p < NC; p++) { e[p] = expf(A[p*NC*NG + c*NG + g] - mx); s += e[p]; }
        float rs = 1.f / s;
        #pragma unroll
        for (int p = 0; p < NC; p++) g_smA[p*NC*NG + c*NG + g] = e[p] * rs;
    }
    {   // B: softmax over m for each (c,g); store transposed [m][g][c]
        float mx = -1e30f;
        #pragma unroll
        for (int m = 0; m < NM; m++) mx = fmaxf(mx, B[c*NM*NG + m*NG + g]);
        float s = 0.f;
        #pragma unroll
        for (int m = 0; m < NM; m++) s += expf(B[c*NM*NG + m*NG + g] - mx);
        float rs = 1.f / s;
        #pragma unroll
        for (int m = 0; m < NM; m++)
            g_smBt[m*NG*NC + g*NC + c] = expf(B[c*NM*NG + m*NG + g] - mx) * rs;
    }
    if (tid < NG) {   // Pi: softmax over c for each g
        int gg = tid;
        float mx = -1e30f;
        #pragma unroll
        for (int cc = 0; cc < NC; cc++) mx = fmaxf(mx, Pi[cc*NG + gg]);
        float s = 0.f;
        #pragma unroll
        for (int cc = 0; cc < NC; cc++) s += expf(Pi[cc*NG + gg] - mx);
        float rs = 1.f / s;
        #pragma unroll
        for (int cc = 0; cc < NC; cc++)
            g_smPi[cc*NG + gg] = expf(Pi[cc*NG + gg] - mx) * rs;
    }
    __syncthreads();
    // leaf nu table: nu(m,g) = sum_c Pi[c,g] * smB[c,m,g]
    for (int i = tid; i < NM*NG; i += 256) {
        int m = i >> 4, gg = i & 15;
        float nu = 0.f;
        #pragma unroll
        for (int cc = 0; cc < NC; cc++)
            nu += g_smPi[cc*NG + gg] * g_smBt[m*NG*NC + gg*NC + cc];
        g_nu[i] = make_float2(1.f / nu, logf(nu));
    }
}

// ---------------------------------------------------------------------------
// Main kernel: one CTA per tree, 3 CTAs/SM.
// Threads: pblk = tid&7 (owns states p = 2*pblk, 2*pblk+1), g = (tid>>3)&15,
// ng = tid>>7 in {0,1}. beta: half [slot][g][c]; leaves fused into level 6.
// ---------------------------------------------------------------------------
__global__ void __launch_bounds__(256, 3)
htmm_upward_kernel(const int* __restrict__ x, float* __restrict__ out) {
    extern __shared__ __align__(16) unsigned char smraw[];
    __half*  sBeta = (__half*)smraw;                                  // 96*256 halfs
    __half*  sBh   = (__half*)(smraw + BETA_HALFS*2);                 // [m][g][c] half
    float2*  sNu   = (float2*)(smraw + BETA_HALFS*2 + B_HALFS*2);     // [m][g]
    __shared__ int   sx[NPT];
    __shared__ float sacc[256];

    const int tid  = threadIdx.x;
    const int tree = blockIdx.x;
    const int pblk = tid & 7;
    const int g    = (tid >> 3) & 15;
    const int ng   = tid >> 7;

    // ---- stage tables ----
    float* Ascr = (float*)smraw;                       // 16KB scratch over beta region
    for (int i = tid; i < NC*NC*NG; i += 256) Ascr[i] = g_smA[i];
    for (int i = tid; i < B_HALFS; i += 256)  sBh[i]  = __float2half_rn(g_smBt[i]);
    for (int i = tid; i < NM*NG; i += 256)    sNu[i]  = g_nu[i];
    for (int i = tid; i < NPT; i += 256)      sx[i]   = x[tree*NPT + i];
    __syncthreads();

    // A rows packed along c pairs for this thread's two states; Pi packed.
    unsigned long long A2[2][8];
    #pragma unroll
    for (int pl = 0; pl < 2; pl++) {
        int p = 2*pblk + pl;
        #pragma unroll
        for (int c2 = 0; c2 < 8; c2++)
            A2[pl][c2] = pack2(Ascr[p*256 + (2*c2)*16 + g],
                               Ascr[p*256 + (2*c2+1)*16 + g]);
    }
    unsigned long long Pi2[8];
    #pragma unroll
    for (int c2 = 0; c2 < 8; c2++)
        Pi2[c2] = pack2(g_smPi[(2*c2)*16 + g], g_smPi[(2*c2+1)*16 + g]);
    __syncthreads();   // A scratch may now be overwritten by level-6 beta

    float accll = 0.f;

    // ---- Level 6 with fused leaves: 64 nodes -> slots [0..64) ----
    for (int j = ng; j < 64; j += 2) {
        const int m0 = sx[127 + 2*j], m1 = sx[128 + 2*j];
        const float2 n0 = sNu[m0*16 + g], n1 = sNu[m1*16 + g];
        const unsigned long long r0 = pack2(n0.x, n0.x);
        const unsigned long long r1 = pack2(n1.x, n1.x);
        const __half2* b0 = (const __half2*)(sBh + m0*256 + g*16);
        const __half2* b1 = (const __half2*)(sBh + m1*256 + g*16);
        unsigned long long a0 = 0ull, a1 = 0ull;
        #pragma unroll
        for (int c2 = 0; c2 < 8; c2++) {
            float2 f0 = __half22float2(b0[c2]);
            float2 f1 = __half22float2(b1[c2]);
            unsigned long long w  = pack2(f0.x, f0.y);
            mul2(w, r0);                                  // B0 * (1/nu0)
            unsigned long long w1 = pack2(f1.x, f1.y);
            ffma2(w, w1, r1);                             // + B1 * (1/nu1)
            mul2(w, Pi2[c2]);                             // * Pi  -> beta0+beta1
            ffma2(a0, A2[0][c2], w);
            ffma2(a1, A2[1][c2], w);
        }
        accll += 0.125f * (n0.y + n1.y);                  // leaf lls from table

        const int mu = sx[63 + j];
        float2 ef = __half22float2(*(const __half2*)(sBh + mu*256 + g*16 + 2*pblk));
        float bv0 = ef.x * unpack_sum(a0);
        float bv1 = ef.y * unpack_sum(a1);
        float s = bv0 + bv1;
        s += __shfl_xor_sync(0xffffffffu, s, 1);
        s += __shfl_xor_sync(0xffffffffu, s, 2);
        s += __shfl_xor_sync(0xffffffffu, s, 4);
        float rs = __fdividef(1.f, s);
        *(__half2*)(sBeta + j*256 + g*16 + 2*pblk) = __floats2half2_rn(bv0*rs, bv1*rs);
        accll += 0.125f * __logf(s);
    }
    __syncthreads();

    // ---- Levels 5..0 ----
    #pragma unroll 1
    for (int l = 5; l >= 0; l--) {
        const int P     = 1 << l;
        const int cbase = ((5 - l) & 1) ? 64 : 0;   // children (level l+1)
        const int pbase = ((6 - l) & 1) ? 64 : 0;   // this level
        for (int j = ng; j < P; j += 2) {
            const uint4* c0 = (const uint4*)(sBeta + (cbase + 2*j    )*256 + g*16);
            const uint4* c1 = (const uint4*)(sBeta + (cbase + 2*j + 1)*256 + g*16);
            uint4 qa0 = c0[0], qa1 = c0[1];
            uint4 qb0 = c1[0], qb1 = c1[1];
            unsigned int ua[8] = {qa0.x,qa0.y,qa0.z,qa0.w, qa1.x,qa1.y,qa1.z,qa1.w};
            unsigned int ub[8] = {qb0.x,qb0.y,qb0.z,qb0.w, qb1.x,qb1.y,qb1.z,qb1.w};
            unsigned long long a0 = 0ull, a1 = 0ull;
            #pragma unroll
            for (int c2 = 0; c2 < 8; c2++) {
                __half2 ha = *(const __half2*)&ua[c2];
                __half2 hb = *(const __half2*)&ub[c2];
                float2 f = __half22float2(__hadd2(ha, hb));   // beta_ch0 + beta_ch1
                unsigned long long w = pack2(f.x, f.y);
                ffma2(a0, A2[0][c2], w);
                ffma2(a1, A2[1][c2], w);
            }
            const int mu = sx[P - 1 + j];
            float2 ef = __half22float2(*(const __half2*)(sBh + mu*256 + g*16 + 2*pblk));
            float bv0 = ef.x * unpack_sum(a0);
            float bv1 = ef.y * unpack_sum(a1);
            float s = bv0 + bv1;
            s += __shfl_xor_sync(0xffffffffu, s, 1);
            s += __shfl_xor_sync(0xffffffffu, s, 2);
            s += __shfl_xor_sync(0xffffffffu, s, 4);
            // nu = 0.5*s; 0.5 cancels in normalization, -ln2 folded at end
            float rs = __fdividef(1.f, s);
            *(__half2*)(sBeta + (pbase + j)*256 + g*16 + 2*pblk) =
                __floats2half2_rn(bv0*rs, bv1*rs);
            accll += 0.125f * __logf(s);
        }
        __syncthreads();
    }

    // ---- Deterministic per-g reduction over the 16 threads sharing g ----
    sacc[tid] = accll;
    __syncthreads();
    if (tid < NG) {
        float s = 0.f;
        #pragma unroll
        for (int k = 0; k < 16; k++)
            s += sacc[(k >> 3)*128 + tid*8 + (k & 7)];
        // 127 non-leaf nodes each owe -ln2 from the folded BF=2 mean
        out[tree*NG + tid] = s - 127.0f * 0.69314718055994530942f;
    }
}

// ---------------------------------------------------------------------------
extern "C" void kernel_launch(void* const* d_in, const int* in_sizes, int n_in,
                              void* d_out, int out_size) {
    const float* A  = (const float*)d_in[0];
    const float* B  = (const float*)d_in[1];
    const float* Pi = (const float*)d_in[2];
    const int*   x  = (const int*)  d_in[3];
    float* out = (float*)d_out;

    cudaFuncSetAttribute(htmm_upward_kernel,
                         cudaFuncAttributeMaxDynamicSharedMemorySize, DYN_BYTES);

    htmm_softmax_kernel<<<1, 256>>>(A, B, Pi);
    htmm_upward_kernel<<<NT, 256, DYN_BYTES>>>(x, out);
}

// round 4
// speedup vs baseline: 1.5146x; 1.5146x over previous
#include <cuda_runtime.h>
#include <math.h>

#define NT 2000
#define NPT 255
#define NC 16
#define NM 32
#define NG 16

typedef unsigned long long ull;

// dynamic shared layout (float offsets)
#define W_R0 0                        // 32 slots (written by levels 6,4,2)
#define W_R1 (32*256)                 // 16 slots (written by levels 5,3,1)
#define W_FLOATS (48*256)             // 48KB: child-pair-sum ping-pong
#define BF_FLOATS (NM*NG*NC)          // 32KB: softmaxed B, [m][g][c]
#define DYN_FLOATS (W_FLOATS + BF_FLOATS + NM*NG*2)
#define DYN_BYTES  (DYN_FLOATS*4)     // 49152+32768+4096 = 86016

__device__ float  g_smA[NC*NC*NG];    // softmaxed A, [p][c][g]
__device__ float  g_smBf[NM*NG*NC];   // softmaxed B, [m][g][c]
__device__ float  g_smPi[NC*NG];      // softmaxed Pi, [c][g]
__device__ float2 g_nu[NM*NG];        // leaf {1/nu, log2 nu} per (m,g)

// ---------------------------------------------------------------------------
// packed f32x2 helpers (FFMA2/FMUL2 only reachable via PTX)
// ---------------------------------------------------------------------------
__device__ __forceinline__ ull pack2(float lo, float hi) {
    ull r; asm("mov.b64 %0, {%1, %2};" : "=l"(r) : "f"(lo), "f"(hi)); return r;
}
__device__ __forceinline__ void ffma2(ull& d, ull a, ull b) {
    asm("fma.rn.f32x2 %0, %1, %2, %0;" : "+l"(d) : "l"(a), "l"(b));
}
__device__ __forceinline__ void mul2(ull& d, ull a) {
    asm("mul.rn.f32x2 %0, %0, %1;" : "+l"(d) : "l"(a));
}
__device__ __forceinline__ float unpack_sum(ull v) {
    float lo, hi; asm("mov.b64 {%0, %1}, %2;" : "=f"(lo), "=f"(hi) : "l"(v));
    return lo + hi;
}

// ---------------------------------------------------------------------------
// Prologue: softmaxes + transposed fp32 B + leaf-nu table. 1 block, 256 thr.
// ---------------------------------------------------------------------------
__global__ void htmm_softmax_kernel(const float* __restrict__ A,
                                    const float* __restrict__ B,
                                    const float* __restrict__ Pi) {
    int tid = threadIdx.x;
    int c = tid >> 4;
    int g = tid & 15;
    {   // A: softmax over p for each (c,g)
        float mx = -1e30f;
        #pragma unroll
        for (int p = 0; p < NC; p++) mx = fmaxf(mx, A[p*NC*NG + c*NG + g]);
        float e[NC]; float s = 0.f;
        #pragma unroll
        for (int p = 0; p < NC; p++) { e[p] = expf(A[p*NC*NG + c*NG + g] - mx); s += e[p]; }
        float rs = 1.f / s;
        #pragma unroll
        for (int p = 0; p < NC; p++) g_smA[p*NC*NG + c*NG + g] = e[p] * rs;
    }
    {   // B: softmax over m for each (c,g); store [m][g][c]
        float mx = -1e30f;
        #pragma unroll
        for (int m = 0; m < NM; m++) mx = fmaxf(mx, B[c*NM*NG + m*NG + g]);
        float s = 0.f;
        #pragma unroll
        for (int m = 0; m < NM; m++) s += expf(B[c*NM*NG + m*NG + g] - mx);
        float rs = 1.f / s;
        #pragma unroll
        for (int m = 0; m < NM; m++)
            g_smBf[m*NG*NC + g*NC + c] = expf(B[c*NM*NG + m*NG + g] - mx) * rs;
    }
    if (tid < NG) {   // Pi: softmax over c for each g
        int gg = tid;
        float mx = -1e30f;
        #pragma unroll
        for (int cc = 0; cc < NC; cc++) mx = fmaxf(mx, Pi[cc*NG + gg]);
        float s = 0.f;
        #pragma unroll
        for (int cc = 0; cc < NC; cc++) s += expf(Pi[cc*NG + gg] - mx);
        float rs = 1.f / s;
        #pragma unroll
        for (int cc = 0; cc < NC; cc++)
            g_smPi[cc*NG + gg] = expf(Pi[cc*NG + gg] - mx) * rs;
    }
    __syncthreads();
    // leaf nu: nu(m,g) = sum_c Pi[c,g]*smB[c,m,g]; store {1/nu, log2 nu}
    for (int i = tid; i < NM*NG; i += 256) {
        int m = i >> 4, gg = i & 15;
        float nu = 0.f;
        #pragma unroll
        for (int cc = 0; cc < NC; cc++)
            nu += g_smPi[cc*NG + gg] * g_smBf[m*NG*NC + gg*NC + cc];
        g_nu[i] = make_float2(1.f / nu, log2f(nu));
    }
}

// ---------------------------------------------------------------------------
// Main kernel: one CTA per tree, 2 CTAs/SM.
// Threads: pblk = tid&3 (owns states p = 4*pblk..4*pblk+3), g = (tid>>2)&15,
// ng = tid>>6 in {0..3}. Iterate over PARENTS: compute both sibling betas,
// store only their sum (what the parent consumes). All fp32, no converts.
// sW slot = [g][c] (256 floats). Level l writes region (l&1)?R1:R0.
// ---------------------------------------------------------------------------
__global__ void __launch_bounds__(256, 2)
htmm_upward_kernel(const int* __restrict__ x, float* __restrict__ out) {
    extern __shared__ __align__(16) float sm[];
    float*  sW  = sm;                               // 48*256 floats
    float*  sBf = sm + W_FLOATS;                    // [m][g][c]
    float2* sNu = (float2*)(sm + W_FLOATS + BF_FLOATS);
    __shared__ int   sx[NPT];
    __shared__ float sacc[256];

    const int tid  = threadIdx.x;
    const int pblk = tid & 3;
    const int g    = (tid >> 2) & 15;
    const int ng   = tid >> 6;

    // ---- stage tables (A via sW scratch — consumed into regs before leaves) ----
    for (int i = tid; i < NC*NC*NG; i += 256) sW[i]  = g_smA[i];
    for (int i = tid; i < BF_FLOATS; i += 256) sBf[i] = g_smBf[i];
    for (int i = tid; i < NM*NG; i += 256)     sNu[i] = g_nu[i];
    for (int i = tid; i < NPT; i += 256)       sx[i]  = x[blockIdx.x*NPT + i];
    __syncthreads();

    // A packed along c-pairs for this thread's states p = 4*pblk+ip
    ull A2[4][8];
    #pragma unroll
    for (int ip = 0; ip < 4; ip++) {
        int p = 4*pblk + ip;
        #pragma unroll
        for (int c2 = 0; c2 < 8; c2++)
            A2[ip][c2] = pack2(sW[p*256 + (2*c2)*16 + g],
                               sW[p*256 + (2*c2+1)*16 + g]);
    }
    ull Pi2[8];
    #pragma unroll
    for (int c2 = 0; c2 < 8; c2++)
        Pi2[c2] = pack2(g_smPi[(2*c2)*16 + g], g_smPi[(2*c2+1)*16 + g]);
    __syncthreads();   // sW scratch may now be overwritten

    float accll = 0.f;   // in log2 units

    // ---- Level 6 (leaves fused): parents k in [0,32), siblings j=2k,2k+1 ----
    for (int k = ng; k < 32; k += 4) {
        float wo0 = 0.f, wo1 = 0.f, wo2 = 0.f, wo3 = 0.f;
        #pragma unroll
        for (int sel = 0; sel < 2; sel++) {
            const int j  = 2*k + sel;                  // level-6 node
            const int m0 = sx[127 + 2*j], m1 = sx[128 + 2*j];
            const float2 n0 = sNu[m0*NG + g], n1 = sNu[m1*NG + g];
            const ull r0 = pack2(n0.x, n0.x);
            const ull r1 = pack2(n1.x, n1.x);
            const ull* b0 = (const ull*)(sBf + m0*256 + g*16);
            const ull* b1 = (const ull*)(sBf + m1*256 + g*16);
            ull a0 = 0ull, a1 = 0ull, a2 = 0ull, a3 = 0ull;
            #pragma unroll
            for (int c2 = 0; c2 < 8; c2++) {
                ull w = b0[c2];
                mul2(w, r0);                 // B(m0)/nu0
                ffma2(w, b1[c2], r1);        // + B(m1)/nu1
                mul2(w, Pi2[c2]);            // * Pi  = beta_leaf0 + beta_leaf1
                ffma2(a0, A2[0][c2], w);
                ffma2(a1, A2[1][c2], w);
                ffma2(a2, A2[2][c2], w);
                ffma2(a3, A2[3][c2], w);
            }
            accll += 0.25f * (n0.y + n1.y);            // leaf lls (log2)

            const int mu = sx[63 + j];
            const float4 e4 = *(const float4*)(sBf + mu*256 + g*16 + 4*pblk);
            float bv0 = e4.x * unpack_sum(a0);
            float bv1 = e4.y * unpack_sum(a1);
            float bv2 = e4.z * unpack_sum(a2);
            float bv3 = e4.w * unpack_sum(a3);
            float s = (bv0 + bv1) + (bv2 + bv3);
            s += __shfl_xor_sync(0xffffffffu, s, 1);
            s += __shfl_xor_sync(0xffffffffu, s, 2);
            float rs = __fdividef(1.f, s);
            wo0 += bv0*rs; wo1 += bv1*rs; wo2 += bv2*rs; wo3 += bv3*rs;
            accll += 0.25f * __log2f(s);
        }
        *(float4*)(sW + W_R0 + k*256 + g*16 + 4*pblk) =
            make_float4(wo0, wo1, wo2, wo3);
    }
    __syncthreads();

    // ---- Levels 5..1 ----
    #pragma unroll 1
    for (int l = 5; l >= 1; l--) {
        const int nPar   = 1 << (l - 1);
        const int rbase  = (l & 1) ? W_R0 : W_R1;   // written by level l+1
        const int wbase  = (l & 1) ? W_R1 : W_R0;
        const int lstart = (1 << l) - 1;
        for (int k = ng; k < nPar; k += 4) {
            float wo0 = 0.f, wo1 = 0.f, wo2 = 0.f, wo3 = 0.f;
            #pragma unroll
            for (int sel = 0; sel < 2; sel++) {
                const int j = 2*k + sel;
                const ull* wv = (const ull*)(sW + rbase + j*256 + g*16);
                ull a0 = 0ull, a1 = 0ull, a2 = 0ull, a3 = 0ull;
                #pragma unroll
                for (int c2 = 0; c2 < 8; c2++) {
                    ull w = wv[c2];                  // beta_ch0+beta_ch1, pre-summed
                    ffma2(a0, A2[0][c2], w);
                    ffma2(a1, A2[1][c2], w);
                    ffma2(a2, A2[2][c2], w);
                    ffma2(a3, A2[3][c2], w);
                }
                const int mu = sx[lstart + j];
                const float4 e4 = *(const float4*)(sBf + mu*256 + g*16 + 4*pblk);
                float bv0 = e4.x * unpack_sum(a0);
                float bv1 = e4.y * unpack_sum(a1);
                float bv2 = e4.z * unpack_sum(a2);
                float bv3 = e4.w * unpack_sum(a3);
                float s = (bv0 + bv1) + (bv2 + bv3);
                s += __shfl_xor_sync(0xffffffffu, s, 1);
                s += __shfl_xor_sync(0xffffffffu, s, 2);
                // true nu = s/2; the /2 cancels in normalization, -1 (log2) folded at end
                float rs = __fdividef(1.f, s);
                wo0 += bv0*rs; wo1 += bv1*rs; wo2 += bv2*rs; wo3 += bv3*rs;
                accll += 0.25f * __log2f(s);
            }
            *(float4*)(sW + wbase + k*256 + g*16 + 4*pblk) =
                make_float4(wo0, wo1, wo2, wo3);
        }
        __syncthreads();
    }

    // ---- Root (level 0): group 0 only, ll contribution only ----
    if (ng == 0) {
        const ull* wv = (const ull*)(sW + W_R1 + g*16);   // level 1 wrote R1 slot 0
        ull a0 = 0ull, a1 = 0ull, a2 = 0ull, a3 = 0ull;
        #pragma unroll
        for (int c2 = 0; c2 < 8; c2++) {
            ull w = wv[c2];
            ffma2(a0, A2[0][c2], w);
            ffma2(a1, A2[1][c2], w);
            ffma2(a2, A2[2][c2], w);
            ffma2(a3, A2[3][c2], w);
        }
        const int mu = sx[0];
        const float4 e4 = *(const float4*)(sBf + mu*256 + g*16 + 4*pblk);
        float s = (e4.x*unpack_sum(a0) + e4.y*unpack_sum(a1))
                + (e4.z*unpack_sum(a2) + e4.w*unpack_sum(a3));
        s += __shfl_xor_sync(0xffffffffu, s, 1);
        s += __shfl_xor_sync(0xffffffffu, s, 2);
        accll += 0.25f * __log2f(s);
    }

    // ---- Deterministic per-g reduction over the 16 threads sharing g ----
    sacc[tid] = accll;
    __syncthreads();
    if (tid < NG) {
        float s = 0.f;
        #pragma unroll
        for (int kk = 0; kk < 16; kk++)
            s += sacc[(kk >> 2)*64 + tid*4 + (kk & 3)];
        // 127 internal nodes each owe -1 in log2 (folded BF=2 mean); convert to ln
        out[blockIdx.x*NG + tid] = 0.69314718055994530942f * (s - 127.0f);
    }
}

// ---------------------------------------------------------------------------
extern "C" void kernel_launch(void* const* d_in, const int* in_sizes, int n_in,
                              void* d_out, int out_size) {
    const float* A  = (const float*)d_in[0];
    const float* B  = (const float*)d_in[1];
    const float* Pi = (const float*)d_in[2];
    const int*   x  = (const int*)  d_in[3];
    float* out = (float*)d_out;

    cudaFuncSetAttribute(htmm_upward_kernel,
                         cudaFuncAttributeMaxDynamicSharedMemorySize, DYN_BYTES);

    htmm_softmax_kernel<<<1, 256>>>(A, B, Pi);
    htmm_upward_kernel<<<NT, 256, DYN_BYTES>>>(x, out);
}